// round 3
// baseline (speedup 1.0000x reference)
#include <cuda_runtime.h>

#define NN 50000
#define EE 800000

// ---------------- scratch (static device globals; no allocation) ----------------
__device__ int   g_is64;           // 1 if edge_index is int64, 0 if int32
__device__ int   g_cnt[NN];
__device__ int   g_fill[NN];
__device__ int   g_rowptr[NN + 1];
__device__ int   g_col[EE];
__device__ __align__(16) float g_dinv[NN];
__device__ __align__(16) float g_h1[NN * 128];   // x @ W1
__device__ __align__(16) float g_hb[NN * 128];   // relu(agg(h1) + b1)
__device__ __align__(16) float g_t2[NN * 64];    // hb @ W2

// ---------------- dtype sniff: int64 edge_index has zero high words ----------------
__global__ void k_sniff(const unsigned* __restrict__ w) {
    if (threadIdx.x == 0 && blockIdx.x == 0) {
        int all0 = 1;
        for (int k = 0; k < 64; k++)
            if (w[2 * k + 1] != 0u) { all0 = 0; break; }
        g_is64 = all0;
    }
}

__device__ __forceinline__ int edge_val(const void* ei, long long idx) {
    // idx in [0, 2*EE): flattened [2, E] array
    int v;
    if (g_is64) v = (int)((const long long*)ei)[idx];
    else        v = ((const int*)ei)[idx];
    // defensive clamp (no-op on valid data, prevents traps on surprises)
    if (v < 0) v = 0;
    if (v >= NN) v = NN - 1;
    return v;
}

// ---------------- CSR build ----------------
__global__ void k_zero() {
    int i = blockIdx.x * blockDim.x + threadIdx.x;
    if (i < NN) { g_cnt[i] = 0; g_fill[i] = 0; }
}

__global__ void k_count(const void* __restrict__ ei) {
    int e = blockIdx.x * blockDim.x + threadIdx.x;
    if (e < EE) {
        int d = edge_val(ei, (long long)EE + e);
        atomicAdd(&g_cnt[d], 1);
    }
}

// Single-block exclusive scan of g_cnt -> g_rowptr, plus dinv = rsqrt(deg+1).
__global__ __launch_bounds__(1024) void k_scan() {
    __shared__ int sums[1024];
    int tid = threadIdx.x;
    const int chunk = (NN + 1023) / 1024;  // 49
    int start = tid * chunk;
    int end   = start + chunk; if (end > NN) end = NN; if (start > NN) start = NN;
    int s = 0;
    for (int i = start; i < end; i++) {
        int c = g_cnt[i];
        s += c;
        g_dinv[i] = rsqrtf((float)(c + 1));  // +1 self loop
    }
    sums[tid] = s;
    __syncthreads();
    for (int off = 1; off < 1024; off <<= 1) {
        int v = (tid >= off) ? sums[tid - off] : 0;
        __syncthreads();
        sums[tid] += v;
        __syncthreads();
    }
    int run = (tid > 0) ? sums[tid - 1] : 0;
    for (int i = start; i < end; i++) {
        g_rowptr[i] = run;
        run += g_cnt[i];
    }
    if (tid == 1023) g_rowptr[NN] = run;  // == EE
}

__global__ void k_scatter(const void* __restrict__ ei) {
    int e = blockIdx.x * blockDim.x + threadIdx.x;
    if (e < EE) {
        int s = edge_val(ei, e);
        int d = edge_val(ei, (long long)EE + e);
        int p = g_rowptr[d] + atomicAdd(&g_fill[d], 1);
        g_col[p] = s;
    }
}

// ---------------- dense GEMM: Y[N,CO] = X[N,128] @ W[128,CO] ----------------
// Block tile: 32 rows x 64 cols (grid.y picks the 64-col half). 256 threads,
// each computes 4 rows x 2 cols. W-slice (32KB) + X-tile (16KB) in smem (=48KB).
template <int CO, int XSEL, int YSEL>
__global__ __launch_bounds__(256) void k_gemm(const float* __restrict__ Xext,
                                              const float* __restrict__ W) {
    const float* X = (XSEL == 0) ? Xext : g_hb;
    float*       Y = (YSEL == 0) ? g_h1 : g_t2;

    __shared__ __align__(16) float Ws[128 * 64];
    __shared__ __align__(16) float Xs[32 * 128];
    int tid  = threadIdx.x;
    int row0 = blockIdx.x * 32;
    int c0   = blockIdx.y * 64;

    // load W[:, c0:c0+64] as [128][64]
    for (int i = tid; i < 128 * 32; i += 256) {        // float2 elements
        int j  = i >> 5;
        int c2 = i & 31;
        ((float2*)Ws)[j * 32 + c2] =
            *(const float2*)(W + (size_t)j * CO + c0 + c2 * 2);
    }
    // load X[row0:row0+32, :] as [32][128]
    for (int i = tid; i < 32 * 32; i += 256) {         // float4 elements
        int r  = i >> 5;
        int j4 = i & 31;
        float4 v = make_float4(0.f, 0.f, 0.f, 0.f);
        if (row0 + r < NN)
            v = ((const float4*)(X + (size_t)(row0 + r) * 128))[j4];
        ((float4*)Xs)[r * 32 + j4] = v;
    }
    __syncthreads();

    int tx = tid & 31;   // col pair
    int ty = tid >> 5;   // row quad (0..7)
    float acc00 = 0.f, acc01 = 0.f, acc10 = 0.f, acc11 = 0.f;
    float acc20 = 0.f, acc21 = 0.f, acc30 = 0.f, acc31 = 0.f;
    const float*  xb = Xs + ty * 4 * 128;
    const float2* wb = (const float2*)Ws;
    #pragma unroll 8
    for (int j = 0; j < 128; j++) {
        float2 w  = wb[j * 32 + tx];
        float  x0 = xb[j];
        float  x1 = xb[128 + j];
        float  x2 = xb[256 + j];
        float  x3 = xb[384 + j];
        acc00 += x0 * w.x; acc01 += x0 * w.y;
        acc10 += x1 * w.x; acc11 += x1 * w.y;
        acc20 += x2 * w.x; acc21 += x2 * w.y;
        acc30 += x3 * w.x; acc31 += x3 * w.y;
    }
    float2 res[4] = { {acc00, acc01}, {acc10, acc11}, {acc20, acc21}, {acc30, acc31} };
    #pragma unroll
    for (int i = 0; i < 4; i++) {
        int r = row0 + ty * 4 + i;
        if (r < NN)
            *(float2*)(Y + (size_t)r * CO + c0 + tx * 2) = res[i];
    }
}

// ---------------- CSR aggregation: one warp per destination node ----------------
// out[i] = (maybe relu)( sum_{s in adj(i)} src[s]*dinv[s]*dinv[i]
//                        + src[i]*dinv[i]^2 + bias )
//   layer 1 (SSEL=0): src = g_h1, dst = g_hb (RELU)
//   layer 2 (SSEL=1): src = g_t2, dst = external out (no RELU)
template <int C, bool RELU, int SSEL>
__global__ __launch_bounds__(256) void k_agg(const float* __restrict__ bias,
                                             float* __restrict__ outext) {
    const float* src = (SSEL == 0) ? g_h1 : g_t2;
    float*       out = (SSEL == 0) ? g_hb : outext;

    int w    = (blockIdx.x * 256 + threadIdx.x) >> 5;
    int lane = threadIdx.x & 31;
    if (w >= NN) return;
    constexpr int V = C / 32;           // 4 (C=128) or 2 (C=64)
    float di = g_dinv[w];
    float acc[V];

    // self loop
    {
        float sn = di * di;
        const float* p = src + (size_t)w * C + lane * V;
        if (V == 4) {
            float4 v = *(const float4*)p;
            acc[0] = v.x * sn; acc[1] = v.y * sn;
            acc[2] = v.z * sn; acc[3] = v.w * sn;
        } else {
            float2 v = *(const float2*)p;
            acc[0] = v.x * sn; acc[1] = v.y * sn;
        }
    }

    int beg = g_rowptr[w];
    int end = g_rowptr[w + 1];
    for (int j = beg; j < end; j++) {
        int   s   = g_col[j];
        float nrm = g_dinv[s] * di;
        const float* p = src + (size_t)s * C + lane * V;
        if (V == 4) {
            float4 v = *(const float4*)p;
            acc[0] += v.x * nrm; acc[1] += v.y * nrm;
            acc[2] += v.z * nrm; acc[3] += v.w * nrm;
        } else {
            float2 v = *(const float2*)p;
            acc[0] += v.x * nrm; acc[1] += v.y * nrm;
        }
    }

    #pragma unroll
    for (int k = 0; k < V; k++) {
        float r = acc[k] + bias[lane * V + k];
        if (RELU) r = fmaxf(r, 0.f);
        out[(size_t)w * C + lane * V + k] = r;
    }
}

// ---------------- launch ----------------
extern "C" void kernel_launch(void* const* d_in, const int* in_sizes, int n_in,
                              void* d_out, int out_size) {
    const float* x   = (const float*)d_in[0];
    const void*  ei  = d_in[1];
    const float* W1  = (const float*)d_in[2];
    const float* b1  = (const float*)d_in[3];
    const float* W2  = (const float*)d_in[4];
    const float* b2  = (const float*)d_in[5];
    float*       out = (float*)d_out;

    // detect edge_index dtype, then build CSR
    k_sniff<<<1, 32>>>((const unsigned*)ei);
    k_zero<<<(NN + 255) / 256, 256>>>();
    k_count<<<(EE + 255) / 256, 256>>>(ei);
    k_scan<<<1, 1024>>>();
    k_scatter<<<(EE + 255) / 256, 256>>>(ei);

    // layer 1: h1 = x @ W1 ; hb = relu(agg(h1) + b1)
    dim3 g1((NN + 31) / 32, 2);
    k_gemm<128, 0, 0><<<g1, 256>>>(x, W1);
    k_agg<128, true, 0><<<(NN * 32 + 255) / 256, 256>>>(b1, nullptr);

    // layer 2: t2 = hb @ W2 ; out = agg(t2) + b2
    dim3 g2((NN + 31) / 32, 1);
    k_gemm<64, 1, 1><<<g2, 256>>>(nullptr, W2);
    k_agg<64, false, 1><<<(NN * 32 + 255) / 256, 256>>>(b2, out);
}

// round 5
// speedup vs baseline: 1.3636x; 1.3636x over previous
#include <cuda_runtime.h>

#define NN 50000
#define EE 800000
#define NB_SCAN 49   // ceil(50000/1024)

// ---------------- scratch (static device globals; no allocation) ----------------
__device__ int   g_is64;           // 1 if edge_index is int64, 0 if int32
__device__ int   g_cnt[NN];
__device__ int   g_fill[NN];
__device__ int   g_rowptr[NN + 1];
__device__ int   g_col[EE];
__device__ int   g_bsum[64];
__device__ int   g_boff[64];
__device__ __align__(16) float g_dinv[NN];
__device__ __align__(16) float g_h1[NN * 128];   // x @ W1
__device__ __align__(16) float g_hb[NN * 128];   // relu(agg(h1) + b1)
__device__ __align__(16) float g_t2[NN * 64];    // hb @ W2

// ---------------- dtype sniff: int64 edge_index has zero high words ----------------
__global__ void k_sniff(const unsigned* __restrict__ w) {
    if (threadIdx.x == 0 && blockIdx.x == 0) {
        int all0 = 1;
        for (int k = 0; k < 64; k++)
            if (w[2 * k + 1] != 0u) { all0 = 0; break; }
        g_is64 = all0;
    }
}

__device__ __forceinline__ int edge_val(const void* ei, long long idx) {
    int v;
    if (g_is64) v = (int)((const long long*)ei)[idx];
    else        v = ((const int*)ei)[idx];
    if (v < 0) v = 0;
    if (v >= NN) v = NN - 1;
    return v;
}

// ---------------- CSR build ----------------
__global__ void k_zero() {
    int i = blockIdx.x * blockDim.x + threadIdx.x;
    if (i < NN) { g_cnt[i] = 0; g_fill[i] = 0; }
}

__global__ void k_count(const void* __restrict__ ei) {
    int e = blockIdx.x * blockDim.x + threadIdx.x;
    if (e < EE) {
        int d = edge_val(ei, (long long)EE + e);
        atomicAdd(&g_cnt[d], 1);
    }
}

// Pass 1: per-block sums of g_cnt (1024 elems per block)
__global__ __launch_bounds__(1024) void k_bsum() {
    __shared__ int s[32];
    int t = threadIdx.x;
    int i = blockIdx.x * 1024 + t;
    int c = (i < NN) ? g_cnt[i] : 0;
    int v = c;
    #pragma unroll
    for (int off = 16; off > 0; off >>= 1)
        v += __shfl_down_sync(0xffffffffu, v, off);
    if ((t & 31) == 0) s[t >> 5] = v;
    __syncthreads();
    if (t < 32) {
        int w = s[t];
        #pragma unroll
        for (int off = 16; off > 0; off >>= 1)
            w += __shfl_down_sync(0xffffffffu, w, off);
        if (t == 0) g_bsum[blockIdx.x] = w;
    }
}

// Pass 2: exclusive scan of the (<=64) block sums, one tiny block
__global__ void k_boff() {
    __shared__ int sh[64];
    int t = threadIdx.x;
    int v = (t < NB_SCAN) ? g_bsum[t] : 0;
    sh[t] = v;
    __syncthreads();
    #pragma unroll
    for (int off = 1; off < 64; off <<= 1) {
        int u = (t >= off) ? sh[t - off] : 0;
        __syncthreads();
        sh[t] += u;
        __syncthreads();
    }
    g_boff[t] = sh[t] - v;   // exclusive
}

// Pass 3: per-block exclusive scan + block offset -> rowptr, plus dinv
__global__ __launch_bounds__(1024) void k_rowptr() {
    __shared__ int sh[1024];
    int t = threadIdx.x;
    int i = blockIdx.x * 1024 + t;
    int c = (i < NN) ? g_cnt[i] : 0;
    sh[t] = c;
    __syncthreads();
    #pragma unroll
    for (int off = 1; off < 1024; off <<= 1) {
        int u = (t >= off) ? sh[t - off] : 0;
        __syncthreads();
        sh[t] += u;
        __syncthreads();
    }
    if (i < NN) {
        g_rowptr[i] = sh[t] - c + g_boff[blockIdx.x];
        g_dinv[i]   = rsqrtf((float)(c + 1));   // +1 self loop
    }
    if (i == 0) g_rowptr[NN] = EE;              // total in-degree == E
}

__global__ void k_scatter(const void* __restrict__ ei) {
    int e = blockIdx.x * blockDim.x + threadIdx.x;
    if (e < EE) {
        int s = edge_val(ei, e);
        int d = edge_val(ei, (long long)EE + e);
        int p = g_rowptr[d] + atomicAdd(&g_fill[d], 1);
        g_col[p] = s;
    }
}

// ---------------- dense GEMM: Y[N,CO] = X[N,128] @ W[128,CO] ----------------
template <int CO, int XSEL, int YSEL>
__global__ __launch_bounds__(256) void k_gemm(const float* __restrict__ Xext,
                                              const float* __restrict__ W) {
    const float* X = (XSEL == 0) ? Xext : g_hb;
    float*       Y = (YSEL == 0) ? g_h1 : g_t2;

    __shared__ __align__(16) float Ws[128 * 64];
    __shared__ __align__(16) float Xs[32 * 128];
    int tid  = threadIdx.x;
    int row0 = blockIdx.x * 32;
    int c0   = blockIdx.y * 64;

    for (int i = tid; i < 128 * 32; i += 256) {        // W slice, float2
        int j  = i >> 5;
        int c2 = i & 31;
        ((float2*)Ws)[j * 32 + c2] =
            *(const float2*)(W + (size_t)j * CO + c0 + c2 * 2);
    }
    for (int i = tid; i < 32 * 32; i += 256) {         // X tile, float4
        int r  = i >> 5;
        int j4 = i & 31;
        float4 v = make_float4(0.f, 0.f, 0.f, 0.f);
        if (row0 + r < NN)
            v = ((const float4*)(X + (size_t)(row0 + r) * 128))[j4];
        ((float4*)Xs)[r * 32 + j4] = v;
    }
    __syncthreads();

    int tx = tid & 31;
    int ty = tid >> 5;
    float acc00 = 0.f, acc01 = 0.f, acc10 = 0.f, acc11 = 0.f;
    float acc20 = 0.f, acc21 = 0.f, acc30 = 0.f, acc31 = 0.f;
    const float*  xb = Xs + ty * 4 * 128;
    const float2* wb = (const float2*)Ws;
    #pragma unroll 8
    for (int j = 0; j < 128; j++) {
        float2 w  = wb[j * 32 + tx];
        float  x0 = xb[j];
        float  x1 = xb[128 + j];
        float  x2 = xb[256 + j];
        float  x3 = xb[384 + j];
        acc00 += x0 * w.x; acc01 += x0 * w.y;
        acc10 += x1 * w.x; acc11 += x1 * w.y;
        acc20 += x2 * w.x; acc21 += x2 * w.y;
        acc30 += x3 * w.x; acc31 += x3 * w.y;
    }
    float2 res[4] = { {acc00, acc01}, {acc10, acc11}, {acc20, acc21}, {acc30, acc31} };
    #pragma unroll
    for (int i = 0; i < 4; i++) {
        int r = row0 + ty * 4 + i;
        if (r < NN)
            *(float2*)(Y + (size_t)r * CO + c0 + tx * 2) = res[i];
    }
}

// ---------------- CSR aggregation: one warp per destination node ----------------
template <int C, bool RELU, int SSEL>
__global__ __launch_bounds__(256) void k_agg(const float* __restrict__ bias,
                                             float* __restrict__ outext) {
    const float* src = (SSEL == 0) ? g_h1 : g_t2;
    float*       out = (SSEL == 0) ? g_hb : outext;

    int w    = (blockIdx.x * 256 + threadIdx.x) >> 5;
    int lane = threadIdx.x & 31;
    if (w >= NN) return;
    constexpr int V = C / 32;           // 4 (C=128) or 2 (C=64)
    float di = g_dinv[w];
    float acc[V];

    {   // self loop
        float sn = di * di;
        const float* p = src + (size_t)w * C + lane * V;
        if (V == 4) {
            float4 v = *(const float4*)p;
            acc[0] = v.x * sn; acc[1] = v.y * sn;
            acc[2] = v.z * sn; acc[3] = v.w * sn;
        } else {
            float2 v = *(const float2*)p;
            acc[0] = v.x * sn; acc[1] = v.y * sn;
        }
    }

    int beg = g_rowptr[w];
    int end = g_rowptr[w + 1];
    for (int j = beg; j < end; j++) {
        int   s   = g_col[j];
        float nrm = g_dinv[s] * di;
        const float* p = src + (size_t)s * C + lane * V;
        if (V == 4) {
            float4 v = *(const float4*)p;
            acc[0] += v.x * nrm; acc[1] += v.y * nrm;
            acc[2] += v.z * nrm; acc[3] += v.w * nrm;
        } else {
            float2 v = *(const float2*)p;
            acc[0] += v.x * nrm; acc[1] += v.y * nrm;
        }
    }

    #pragma unroll
    for (int k = 0; k < V; k++) {
        float r = acc[k] + bias[lane * V + k];
        if (RELU) r = fmaxf(r, 0.f);
        out[(size_t)w * C + lane * V + k] = r;
    }
}

// ---------------- launch ----------------
extern "C" void kernel_launch(void* const* d_in, const int* in_sizes, int n_in,
                              void* d_out, int out_size) {
    const float* x   = (const float*)d_in[0];
    const void*  ei  = d_in[1];
    const float* W1  = (const float*)d_in[2];
    const float* b1  = (const float*)d_in[3];
    const float* W2  = (const float*)d_in[4];
    const float* b2  = (const float*)d_in[5];
    float*       out = (float*)d_out;

    // detect edge_index dtype, then build CSR
    k_sniff<<<1, 32>>>((const unsigned*)ei);
    k_zero<<<(NN + 255) / 256, 256>>>();
    k_count<<<(EE + 255) / 256, 256>>>(ei);
    k_bsum<<<NB_SCAN, 1024>>>();
    k_boff<<<1, 64>>>();
    k_rowptr<<<NB_SCAN, 1024>>>();
    k_scatter<<<(EE + 255) / 256, 256>>>(ei);

    // layer 1: h1 = x @ W1 ; hb = relu(agg(h1) + b1)
    dim3 g1((NN + 31) / 32, 2);
    k_gemm<128, 0, 0><<<g1, 256>>>(x, W1);
    k_agg<128, true, 0><<<(NN * 32 + 255) / 256, 256>>>(b1, nullptr);

    // layer 2: t2 = hb @ W2 ; out = agg(t2) + b2
    dim3 g2((NN + 31) / 32, 1);
    k_gemm<64, 1, 1><<<g2, 256>>>(nullptr, W2);
    k_agg<64, false, 1><<<(NN * 32 + 255) / 256, 256>>>(b2, out);
}

// round 6
// speedup vs baseline: 1.7963x; 1.3173x over previous
#include <cuda_runtime.h>

#define NN 50000
#define EE 800000
#define NB_SCAN 49   // ceil(50000/1024)

// ---------------- scratch (static device globals; no allocation) ----------------
__device__ int   g_is64;
__device__ int   g_cnt[NN];
__device__ int   g_fill[NN];
__device__ int   g_rowptr[NN + 1];
__device__ int   g_col[EE];
__device__ int   g_bsum[64];
__device__ int   g_boff[64];
__device__ __align__(16) float g_dinv[NN];
__device__ __align__(16) float g_h1[NN * 128];
__device__ __align__(16) float g_hb[NN * 128];
__device__ __align__(16) float g_t2[NN * 64];

// packed f32x2 helpers
#define FMA_F32X2(d, a, b, c) \
    asm("fma.rn.f32x2 %0, %1, %2, %3;" : "=l"(d) : "l"(a), "l"(b), "l"(c))
#define PACK_DUP(out, w) \
    asm("mov.b64 %0, {%1, %2};" : "=l"(out) : "f"(w), "f"(w))

// ---------------- dtype sniff ----------------
__global__ void k_sniff(const unsigned* __restrict__ w) {
    if (threadIdx.x == 0 && blockIdx.x == 0) {
        int all0 = 1;
        for (int k = 0; k < 64; k++)
            if (w[2 * k + 1] != 0u) { all0 = 0; break; }
        g_is64 = all0;
    }
}

__device__ __forceinline__ int edge_val(const void* ei, long long idx) {
    int v;
    if (g_is64) v = (int)((const long long*)ei)[idx];
    else        v = ((const int*)ei)[idx];
    if (v < 0) v = 0;
    if (v >= NN) v = NN - 1;
    return v;
}

// ---------------- CSR build ----------------
__global__ void k_zero() {
    int i = blockIdx.x * blockDim.x + threadIdx.x;
    if (i < NN) { g_cnt[i] = 0; g_fill[i] = 0; }
}

__global__ void k_count(const void* __restrict__ ei) {
    int e = blockIdx.x * blockDim.x + threadIdx.x;
    if (e < EE) {
        int d = edge_val(ei, (long long)EE + e);
        atomicAdd(&g_cnt[d], 1);
    }
}

__global__ __launch_bounds__(1024) void k_bsum() {
    __shared__ int s[32];
    int t = threadIdx.x;
    int i = blockIdx.x * 1024 + t;
    int c = (i < NN) ? g_cnt[i] : 0;
    int v = c;
    #pragma unroll
    for (int off = 16; off > 0; off >>= 1)
        v += __shfl_down_sync(0xffffffffu, v, off);
    if ((t & 31) == 0) s[t >> 5] = v;
    __syncthreads();
    if (t < 32) {
        int w = s[t];
        #pragma unroll
        for (int off = 16; off > 0; off >>= 1)
            w += __shfl_down_sync(0xffffffffu, w, off);
        if (t == 0) g_bsum[blockIdx.x] = w;
    }
}

__global__ void k_boff() {
    __shared__ int sh[64];
    int t = threadIdx.x;
    int v = (t < NB_SCAN) ? g_bsum[t] : 0;
    sh[t] = v;
    __syncthreads();
    #pragma unroll
    for (int off = 1; off < 64; off <<= 1) {
        int u = (t >= off) ? sh[t - off] : 0;
        __syncthreads();
        sh[t] += u;
        __syncthreads();
    }
    g_boff[t] = sh[t] - v;
}

__global__ __launch_bounds__(1024) void k_rowptr() {
    __shared__ int sh[1024];
    int t = threadIdx.x;
    int i = blockIdx.x * 1024 + t;
    int c = (i < NN) ? g_cnt[i] : 0;
    sh[t] = c;
    __syncthreads();
    #pragma unroll
    for (int off = 1; off < 1024; off <<= 1) {
        int u = (t >= off) ? sh[t - off] : 0;
        __syncthreads();
        sh[t] += u;
        __syncthreads();
    }
    if (i < NN) {
        g_rowptr[i] = sh[t] - c + g_boff[blockIdx.x];
        g_dinv[i]   = rsqrtf((float)(c + 1));
    }
    if (i == 0) g_rowptr[NN] = EE;
}

__global__ void k_scatter(const void* __restrict__ ei) {
    int e = blockIdx.x * blockDim.x + threadIdx.x;
    if (e < EE) {
        int s = edge_val(ei, e);
        int d = edge_val(ei, (long long)EE + e);
        int p = g_rowptr[d] + atomicAdd(&g_fill[d], 1);
        g_col[p] = s;
    }
}

// ---------------- GEMM v2: Y[N,CO] = X[N,128] @ W[128,CO], packed f32x2 ----------------
// Tile: 128 rows x 64 cols, 256 threads, K chunked by 32 with transposed X smem.
// Thread (tx=tid&15, ty=tid>>4): rows ty*8..+7 (as 4 row-pairs), cols tx*4..+3.
template <int CO, int XSEL, int YSEL>
__global__ __launch_bounds__(256) void k_gemm2(const float* __restrict__ Xext,
                                               const float* __restrict__ W) {
    const float* X = (XSEL == 0) ? Xext : g_hb;
    float*       Y = (YSEL == 0) ? g_h1 : g_t2;

    __shared__ float Xt[32][130];   // [j][row], pad 130 (even: LDS.64-aligned, low conflicts)
    __shared__ __align__(16) float Ws[32][64];

    int tid  = threadIdx.x;
    int row0 = blockIdx.x * 128;
    int c0   = blockIdx.y * 64;
    int tx   = tid & 15;
    int ty   = tid >> 4;

    unsigned long long acc[4][4];   // [row-pair][col]
    #pragma unroll
    for (int p = 0; p < 4; p++)
        #pragma unroll
        for (int c = 0; c < 4; c++) acc[p][c] = 0ull;

    for (int ch = 0; ch < 4; ch++) {
        // W chunk: rows ch*32..+31, cols c0..c0+63 (coalesced float2)
        #pragma unroll
        for (int it = 0; it < 4; it++) {
            int idx = it * 256 + tid;        // 1024 float2
            int cc2 = idx & 31;
            int jj  = idx >> 5;
            *(float2*)&Ws[jj][cc2 * 2] =
                *(const float2*)(W + (size_t)(ch * 32 + jj) * CO + c0 + cc2 * 2);
        }
        // X chunk transposed: Xt[j][r] (coalesced float4 loads)
        #pragma unroll
        for (int it = 0; it < 4; it++) {
            int idx = it * 256 + tid;        // 1024 float4
            int j4  = idx & 7;
            int r   = idx >> 3;
            float4 v = make_float4(0.f, 0.f, 0.f, 0.f);
            if (row0 + r < NN)
                v = *(const float4*)(X + (size_t)(row0 + r) * 128 + ch * 32 + j4 * 4);
            Xt[j4 * 4 + 0][r] = v.x;
            Xt[j4 * 4 + 1][r] = v.y;
            Xt[j4 * 4 + 2][r] = v.z;
            Xt[j4 * 4 + 3][r] = v.w;
        }
        __syncthreads();

        #pragma unroll
        for (int jj = 0; jj < 32; jj++) {
            unsigned long long a[4];
            #pragma unroll
            for (int p = 0; p < 4; p++)
                a[p] = *(const unsigned long long*)&Xt[jj][ty * 8 + p * 2];
            float4 wv = *(const float4*)&Ws[jj][tx * 4];
            unsigned long long wb[4];
            PACK_DUP(wb[0], wv.x);
            PACK_DUP(wb[1], wv.y);
            PACK_DUP(wb[2], wv.z);
            PACK_DUP(wb[3], wv.w);
            #pragma unroll
            for (int c = 0; c < 4; c++)
                #pragma unroll
                for (int p = 0; p < 4; p++)
                    FMA_F32X2(acc[p][c], a[p], wb[c], acc[p][c]);
        }
        __syncthreads();
    }

    // epilogue: unpack row-pairs, float4 stores
    #pragma unroll
    for (int p = 0; p < 4; p++) {
        int r = row0 + ty * 8 + p * 2;
        float4 lo, hi;
        float* lop = &lo.x; float* hip = &hi.x;
        #pragma unroll
        for (int c = 0; c < 4; c++) {
            lop[c] = __uint_as_float((unsigned)(acc[p][c] & 0xffffffffull));
            hip[c] = __uint_as_float((unsigned)(acc[p][c] >> 32));
        }
        if (r < NN)     *(float4*)(Y + (size_t)r * CO + c0 + tx * 4)       = lo;
        if (r + 1 < NN) *(float4*)(Y + (size_t)(r + 1) * CO + c0 + tx * 4) = hi;
    }
}

// ---------------- CSR aggregation: warp per dst, x4 unrolled (MLP=4) ----------------
template <int C, bool RELU, int SSEL>
__global__ __launch_bounds__(256) void k_agg(const float* __restrict__ bias,
                                             float* __restrict__ outext) {
    const float* src = (SSEL == 0) ? g_h1 : g_t2;
    float*       out = (SSEL == 0) ? g_hb : outext;

    int w    = (blockIdx.x * 256 + threadIdx.x) >> 5;
    int lane = threadIdx.x & 31;
    if (w >= NN) return;
    constexpr int V = C / 32;           // 4 or 2
    float di = g_dinv[w];
    float acc[V];

    {   // self loop
        float sn = di * di;
        const float* p = src + (size_t)w * C + lane * V;
        if (V == 4) {
            float4 v = *(const float4*)p;
            acc[0] = v.x * sn; acc[1] = v.y * sn;
            acc[2] = v.z * sn; acc[3] = v.w * sn;
        } else {
            float2 v = *(const float2*)p;
            acc[0] = v.x * sn; acc[1] = v.y * sn;
        }
    }

    int beg = g_rowptr[w];
    int end = g_rowptr[w + 1];
    int j   = beg;

    for (; j + 4 <= end; j += 4) {
        int s0 = g_col[j + 0], s1 = g_col[j + 1];
        int s2 = g_col[j + 2], s3 = g_col[j + 3];
        float n0 = g_dinv[s0] * di, n1 = g_dinv[s1] * di;
        float n2 = g_dinv[s2] * di, n3 = g_dinv[s3] * di;
        if (V == 4) {
            float4 v0 = *(const float4*)(src + (size_t)s0 * C + lane * 4);
            float4 v1 = *(const float4*)(src + (size_t)s1 * C + lane * 4);
            float4 v2 = *(const float4*)(src + (size_t)s2 * C + lane * 4);
            float4 v3 = *(const float4*)(src + (size_t)s3 * C + lane * 4);
            acc[0] += v0.x * n0; acc[1] += v0.y * n0; acc[2] += v0.z * n0; acc[3] += v0.w * n0;
            acc[0] += v1.x * n1; acc[1] += v1.y * n1; acc[2] += v1.z * n1; acc[3] += v1.w * n1;
            acc[0] += v2.x * n2; acc[1] += v2.y * n2; acc[2] += v2.z * n2; acc[3] += v2.w * n2;
            acc[0] += v3.x * n3; acc[1] += v3.y * n3; acc[2] += v3.z * n3; acc[3] += v3.w * n3;
        } else {
            float2 v0 = *(const float2*)(src + (size_t)s0 * C + lane * 2);
            float2 v1 = *(const float2*)(src + (size_t)s1 * C + lane * 2);
            float2 v2 = *(const float2*)(src + (size_t)s2 * C + lane * 2);
            float2 v3 = *(const float2*)(src + (size_t)s3 * C + lane * 2);
            acc[0] += v0.x * n0; acc[1] += v0.y * n0;
            acc[0] += v1.x * n1; acc[1] += v1.y * n1;
            acc[0] += v2.x * n2; acc[1] += v2.y * n2;
            acc[0] += v3.x * n3; acc[1] += v3.y * n3;
        }
    }
    for (; j < end; j++) {
        int   s   = g_col[j];
        float nrm = g_dinv[s] * di;
        const float* p = src + (size_t)s * C + lane * V;
        if (V == 4) {
            float4 v = *(const float4*)p;
            acc[0] += v.x * nrm; acc[1] += v.y * nrm;
            acc[2] += v.z * nrm; acc[3] += v.w * nrm;
        } else {
            float2 v = *(const float2*)p;
            acc[0] += v.x * nrm; acc[1] += v.y * nrm;
        }
    }

    #pragma unroll
    for (int k = 0; k < V; k++) {
        float r = acc[k] + bias[lane * V + k];
        if (RELU) r = fmaxf(r, 0.f);
        out[(size_t)w * C + lane * V + k] = r;
    }
}

// ---------------- launch ----------------
extern "C" void kernel_launch(void* const* d_in, const int* in_sizes, int n_in,
                              void* d_out, int out_size) {
    const float* x   = (const float*)d_in[0];
    const void*  ei  = d_in[1];
    const float* W1  = (const float*)d_in[2];
    const float* b1  = (const float*)d_in[3];
    const float* W2  = (const float*)d_in[4];
    const float* b2  = (const float*)d_in[5];
    float*       out = (float*)d_out;

    k_sniff<<<1, 32>>>((const unsigned*)ei);
    k_zero<<<(NN + 255) / 256, 256>>>();
    k_count<<<(EE + 255) / 256, 256>>>(ei);
    k_bsum<<<NB_SCAN, 1024>>>();
    k_boff<<<1, 64>>>();
    k_rowptr<<<NB_SCAN, 1024>>>();
    k_scatter<<<(EE + 255) / 256, 256>>>(ei);

    // layer 1
    dim3 g1((NN + 127) / 128, 2);
    k_gemm2<128, 0, 0><<<g1, 256>>>(x, W1);
    k_agg<128, true, 0><<<(NN * 32 + 255) / 256, 256>>>(b1, nullptr);

    // layer 2
    dim3 g2((NN + 127) / 128, 1);
    k_gemm2<64, 1, 1><<<g2, 256>>>(nullptr, W2);
    k_agg<64, false, 1><<<(NN * 32 + 255) / 256, 256>>>(b2, out);
}

// round 7
// speedup vs baseline: 1.9565x; 1.0892x over previous
#include <cuda_runtime.h>

#define NN 50000
#define EE 800000
#define NB_SCAN 49    // ceil(50000/1024)
#define GB1 391       // ceil(50000/128) gemm row-tiles
#define EB2 1563      // ceil(400000/256) edge-pair blocks

// ---------------- scratch ----------------
__device__ int   g_is64;
__device__ int   g_cnt[NN];
__device__ int   g_fill[NN];
__device__ int   g_rowptr[NN + 1];
__device__ int   g_col[EE];
__device__ int   g_bsum[64];
__device__ int   g_boff[64];
__device__ __align__(16) float g_dinv[NN];
__device__ __align__(16) float g_h1[NN * 128];
__device__ __align__(16) float g_hb[NN * 128];
__device__ __align__(16) float g_t2[NN * 64];

#define FMA_F32X2(d, a, b, c) \
    asm("fma.rn.f32x2 %0, %1, %2, %3;" : "=l"(d) : "l"(a), "l"(b), "l"(c))
#define PACK_DUP(out, w) \
    asm("mov.b64 %0, {%1, %2};" : "=l"(out) : "f"(w), "f"(w))

__device__ __forceinline__ int clampn(int v) {
    if (v < 0) v = 0;
    if (v >= NN) v = NN - 1;
    return v;
}

// ---------------- init: zero counters + dtype sniff ----------------
__global__ void k_init(const unsigned* __restrict__ w) {
    int i = blockIdx.x * blockDim.x + threadIdx.x;
    if (i < NN) { g_cnt[i] = 0; g_fill[i] = 0; }
    if (i == 0) {
        int all0 = 1;
        for (int k = 0; k < 64; k++)
            if (w[2 * k + 1] != 0u) { all0 = 0; break; }
        g_is64 = all0;
    }
}

// ---------------- GEMM body: Y[row0..+128, c0..+64] += X[.,128] @ W[128,CO] ----------------
template <int CO, int XSEL, int YSEL>
__device__ __forceinline__ void gemm_body(const float* __restrict__ Xext,
                                          const float* __restrict__ W,
                                          int row0, int c0) {
    const float* X = (XSEL == 0) ? Xext : g_hb;
    float*       Y = (YSEL == 0) ? g_h1 : g_t2;

    __shared__ float Xt[32][130];
    __shared__ __align__(16) float Ws[32][64];

    int tid = threadIdx.x;
    int tx  = tid & 15;
    int ty  = tid >> 4;

    unsigned long long acc[4][4];
    #pragma unroll
    for (int p = 0; p < 4; p++)
        #pragma unroll
        for (int c = 0; c < 4; c++) acc[p][c] = 0ull;

    for (int ch = 0; ch < 4; ch++) {
        #pragma unroll
        for (int it = 0; it < 4; it++) {
            int idx = it * 256 + tid;
            int cc2 = idx & 31;
            int jj  = idx >> 5;
            *(float2*)&Ws[jj][cc2 * 2] =
                *(const float2*)(W + (size_t)(ch * 32 + jj) * CO + c0 + cc2 * 2);
        }
        #pragma unroll
        for (int it = 0; it < 4; it++) {
            int idx = it * 256 + tid;
            int j4  = idx & 7;
            int r   = idx >> 3;
            float4 v = make_float4(0.f, 0.f, 0.f, 0.f);
            if (row0 + r < NN)
                v = *(const float4*)(X + (size_t)(row0 + r) * 128 + ch * 32 + j4 * 4);
            Xt[j4 * 4 + 0][r] = v.x;
            Xt[j4 * 4 + 1][r] = v.y;
            Xt[j4 * 4 + 2][r] = v.z;
            Xt[j4 * 4 + 3][r] = v.w;
        }
        __syncthreads();

        #pragma unroll
        for (int jj = 0; jj < 32; jj++) {
            unsigned long long a[4];
            #pragma unroll
            for (int p = 0; p < 4; p++)
                a[p] = *(const unsigned long long*)&Xt[jj][ty * 8 + p * 2];
            float4 wv = *(const float4*)&Ws[jj][tx * 4];
            unsigned long long wb[4];
            PACK_DUP(wb[0], wv.x);
            PACK_DUP(wb[1], wv.y);
            PACK_DUP(wb[2], wv.z);
            PACK_DUP(wb[3], wv.w);
            #pragma unroll
            for (int c = 0; c < 4; c++)
                #pragma unroll
                for (int p = 0; p < 4; p++)
                    FMA_F32X2(acc[p][c], a[p], wb[c], acc[p][c]);
        }
        __syncthreads();
    }

    #pragma unroll
    for (int p = 0; p < 4; p++) {
        int r = row0 + ty * 8 + p * 2;
        float4 lo, hi;
        float* lop = &lo.x; float* hip = &hi.x;
        #pragma unroll
        for (int c = 0; c < 4; c++) {
            lop[c] = __uint_as_float((unsigned)(acc[p][c] & 0xffffffffull));
            hip[c] = __uint_as_float((unsigned)(acc[p][c] >> 32));
        }
        if (r < NN)     *(float4*)(Y + (size_t)r * CO + c0 + tx * 4)       = lo;
        if (r + 1 < NN) *(float4*)(Y + (size_t)(r + 1) * CO + c0 + tx * 4) = hi;
    }
}

// ---------------- fused A: GEMM1 cols 0-63  ||  edge count (2 edges/thread) ----------------
__global__ __launch_bounds__(256) void k_fusedA(const float* __restrict__ x,
                                                const float* __restrict__ W1,
                                                const void* __restrict__ ei) {
    if (blockIdx.x < GB1) {
        gemm_body<128, 0, 0>(x, W1, blockIdx.x * 128, 0);
    } else {
        int idx = (blockIdx.x - GB1) * 256 + threadIdx.x;   // edge pair id
        if (idx < EE / 2) {
            int d0, d1;
            if (g_is64) {
                ulonglong2 p = ((const ulonglong2*)((const char*)ei + (size_t)EE * 8))[idx];
                d0 = clampn((int)p.x); d1 = clampn((int)p.y);
            } else {
                int2 p = ((const int2*)((const char*)ei + (size_t)EE * 4))[idx];
                d0 = clampn(p.x); d1 = clampn(p.y);
            }
            atomicAdd(&g_cnt[d0], 1);
            atomicAdd(&g_cnt[d1], 1);
        }
    }
}

// ---------------- scan (3 passes) ----------------
__global__ __launch_bounds__(1024) void k_bsum() {
    __shared__ int s[32];
    int t = threadIdx.x;
    int i = blockIdx.x * 1024 + t;
    int c = (i < NN) ? g_cnt[i] : 0;
    int v = c;
    #pragma unroll
    for (int off = 16; off > 0; off >>= 1)
        v += __shfl_down_sync(0xffffffffu, v, off);
    if ((t & 31) == 0) s[t >> 5] = v;
    __syncthreads();
    if (t < 32) {
        int w = s[t];
        #pragma unroll
        for (int off = 16; off > 0; off >>= 1)
            w += __shfl_down_sync(0xffffffffu, w, off);
        if (t == 0) g_bsum[blockIdx.x] = w;
    }
}

__global__ void k_boff() {
    __shared__ int sh[64];
    int t = threadIdx.x;
    int v = (t < NB_SCAN) ? g_bsum[t] : 0;
    sh[t] = v;
    __syncthreads();
    #pragma unroll
    for (int off = 1; off < 64; off <<= 1) {
        int u = (t >= off) ? sh[t - off] : 0;
        __syncthreads();
        sh[t] += u;
        __syncthreads();
    }
    g_boff[t] = sh[t] - v;
}

__global__ __launch_bounds__(1024) void k_rowptr() {
    __shared__ int sh[1024];
    int t = threadIdx.x;
    int i = blockIdx.x * 1024 + t;
    int c = (i < NN) ? g_cnt[i] : 0;
    sh[t] = c;
    __syncthreads();
    #pragma unroll
    for (int off = 1; off < 1024; off <<= 1) {
        int u = (t >= off) ? sh[t - off] : 0;
        __syncthreads();
        sh[t] += u;
        __syncthreads();
    }
    if (i < NN) {
        g_rowptr[i] = sh[t] - c + g_boff[blockIdx.x];
        g_dinv[i]   = rsqrtf((float)(c + 1));
    }
    if (i == 0) g_rowptr[NN] = EE;
}

// ---------------- fused B: GEMM1 cols 64-127  ||  edge scatter (2 edges/thread) ----------------
__global__ __launch_bounds__(256) void k_fusedB(const float* __restrict__ x,
                                                const float* __restrict__ W1,
                                                const void* __restrict__ ei) {
    if (blockIdx.x < GB1) {
        gemm_body<128, 0, 0>(x, W1, blockIdx.x * 128, 64);
    } else {
        int idx = (blockIdx.x - GB1) * 256 + threadIdx.x;
        if (idx < EE / 2) {
            int s0, s1, d0, d1;
            if (g_is64) {
                ulonglong2 ps = ((const ulonglong2*)ei)[idx];
                ulonglong2 pd = ((const ulonglong2*)((const char*)ei + (size_t)EE * 8))[idx];
                s0 = clampn((int)ps.x); s1 = clampn((int)ps.y);
                d0 = clampn((int)pd.x); d1 = clampn((int)pd.y);
            } else {
                int2 ps = ((const int2*)ei)[idx];
                int2 pd = ((const int2*)((const char*)ei + (size_t)EE * 4))[idx];
                s0 = clampn(ps.x); s1 = clampn(ps.y);
                d0 = clampn(pd.x); d1 = clampn(pd.y);
            }
            int p0 = g_rowptr[d0] + atomicAdd(&g_fill[d0], 1);
            g_col[p0] = s0;
            int p1 = g_rowptr[d1] + atomicAdd(&g_fill[d1], 1);
            g_col[p1] = s1;
        }
    }
}

// ---------------- standalone GEMM (layer 2) ----------------
template <int CO, int XSEL, int YSEL>
__global__ __launch_bounds__(256) void k_gemm2(const float* __restrict__ Xext,
                                               const float* __restrict__ W) {
    gemm_body<CO, XSEL, YSEL>(Xext, W, blockIdx.x * 128, blockIdx.y * 64);
}

// ---------------- CSR aggregation: warp per dst, x4 unrolled ----------------
template <int C, bool RELU, int SSEL>
__global__ __launch_bounds__(256) void k_agg(const float* __restrict__ bias,
                                             float* __restrict__ outext) {
    const float* src = (SSEL == 0) ? g_h1 : g_t2;
    float*       out = (SSEL == 0) ? g_hb : outext;

    int w    = (blockIdx.x * 256 + threadIdx.x) >> 5;
    int lane = threadIdx.x & 31;
    if (w >= NN) return;
    constexpr int V = C / 32;
    float di = g_dinv[w];
    float acc[V];

    {
        float sn = di * di;
        const float* p = src + (size_t)w * C + lane * V;
        if (V == 4) {
            float4 v = *(const float4*)p;
            acc[0] = v.x * sn; acc[1] = v.y * sn;
            acc[2] = v.z * sn; acc[3] = v.w * sn;
        } else {
            float2 v = *(const float2*)p;
            acc[0] = v.x * sn; acc[1] = v.y * sn;
        }
    }

    int beg = g_rowptr[w];
    int end = g_rowptr[w + 1];
    int j   = beg;

    for (; j + 4 <= end; j += 4) {
        int s0 = g_col[j + 0], s1 = g_col[j + 1];
        int s2 = g_col[j + 2], s3 = g_col[j + 3];
        float n0 = g_dinv[s0] * di, n1 = g_dinv[s1] * di;
        float n2 = g_dinv[s2] * di, n3 = g_dinv[s3] * di;
        if (V == 4) {
            float4 v0 = *(const float4*)(src + (size_t)s0 * C + lane * 4);
            float4 v1 = *(const float4*)(src + (size_t)s1 * C + lane * 4);
            float4 v2 = *(const float4*)(src + (size_t)s2 * C + lane * 4);
            float4 v3 = *(const float4*)(src + (size_t)s3 * C + lane * 4);
            acc[0] += v0.x * n0; acc[1] += v0.y * n0; acc[2] += v0.z * n0; acc[3] += v0.w * n0;
            acc[0] += v1.x * n1; acc[1] += v1.y * n1; acc[2] += v1.z * n1; acc[3] += v1.w * n1;
            acc[0] += v2.x * n2; acc[1] += v2.y * n2; acc[2] += v2.z * n2; acc[3] += v2.w * n2;
            acc[0] += v3.x * n3; acc[1] += v3.y * n3; acc[2] += v3.z * n3; acc[3] += v3.w * n3;
        } else {
            float2 v0 = *(const float2*)(src + (size_t)s0 * C + lane * 2);
            float2 v1 = *(const float2*)(src + (size_t)s1 * C + lane * 2);
            float2 v2 = *(const float2*)(src + (size_t)s2 * C + lane * 2);
            float2 v3 = *(const float2*)(src + (size_t)s3 * C + lane * 2);
            acc[0] += v0.x * n0; acc[1] += v0.y * n0;
            acc[0] += v1.x * n1; acc[1] += v1.y * n1;
            acc[0] += v2.x * n2; acc[1] += v2.y * n2;
            acc[0] += v3.x * n3; acc[1] += v3.y * n3;
        }
    }
    for (; j < end; j++) {
        int   s   = g_col[j];
        float nrm = g_dinv[s] * di;
        const float* p = src + (size_t)s * C + lane * V;
        if (V == 4) {
            float4 v = *(const float4*)p;
            acc[0] += v.x * nrm; acc[1] += v.y * nrm;
            acc[2] += v.z * nrm; acc[3] += v.w * nrm;
        } else {
            float2 v = *(const float2*)p;
            acc[0] += v.x * nrm; acc[1] += v.y * nrm;
        }
    }

    #pragma unroll
    for (int k = 0; k < V; k++) {
        float r = acc[k] + bias[lane * V + k];
        if (RELU) r = fmaxf(r, 0.f);
        out[(size_t)w * C + lane * V + k] = r;
    }
}

// ---------------- launch ----------------
extern "C" void kernel_launch(void* const* d_in, const int* in_sizes, int n_in,
                              void* d_out, int out_size) {
    const float* x   = (const float*)d_in[0];
    const void*  ei  = d_in[1];
    const float* W1  = (const float*)d_in[2];
    const float* b1  = (const float*)d_in[3];
    const float* W2  = (const float*)d_in[4];
    const float* b2  = (const float*)d_in[5];
    float*       out = (float*)d_out;

    k_init<<<(NN + 255) / 256, 256>>>((const unsigned*)ei);
    k_fusedA<<<GB1 + EB2, 256>>>(x, W1, ei);   // gemm1 half0 || count
    k_bsum<<<NB_SCAN, 1024>>>();
    k_boff<<<1, 64>>>();
    k_rowptr<<<NB_SCAN, 1024>>>();
    k_fusedB<<<GB1 + EB2, 256>>>(x, W1, ei);   // gemm1 half1 || scatter

    k_agg<128, true, 0><<<(NN * 32 + 255) / 256, 256>>>(b1, nullptr);

    dim3 g2(GB1, 1);
    k_gemm2<64, 1, 1><<<g2, 256>>>(nullptr, W2);
    k_agg<64, false, 1><<<(NN * 32 + 255) / 256, 256>>>(b2, out);
}

// round 8
// speedup vs baseline: 2.1114x; 1.0792x over previous
#include <cuda_runtime.h>
#include <cuda_fp16.h>

#define NN 50000
#define EE 800000
#define NB_SCAN 49    // ceil(50000/1024)
#define GB1 391       // ceil(50000/128) gemm row-tiles
#define EB2 1563      // ceil(400000/256) edge-pair blocks

// ---------------- scratch ----------------
__device__ int   g_is64;
__device__ int   g_cnt[NN];
__device__ int   g_fill[NN];
__device__ int   g_rowptr[NN + 1];
__device__ int   g_col[EE];
__device__ int   g_bsum[64];
__device__ __align__(16) float  g_dinv[NN];
__device__ __align__(16) __half g_h1h[NN * 128];   // x @ W1, fp16 storage
__device__ __align__(16) float  g_hb[NN * 128];    // relu(agg1 + b1), fp32
__device__ __align__(16) float  g_t2[NN * 64];     // hb @ W2, fp32

#define FMA_F32X2(d, a, b, c) \
    asm("fma.rn.f32x2 %0, %1, %2, %3;" : "=l"(d) : "l"(a), "l"(b), "l"(c))
#define PACK_DUP(out, w) \
    asm("mov.b64 %0, {%1, %2};" : "=l"(out) : "f"(w), "f"(w))

__device__ __forceinline__ int clampn(int v) {
    if (v < 0) v = 0;
    if (v >= NN) v = NN - 1;
    return v;
}

// ---------------- init: zero counters + dtype sniff ----------------
__global__ void k_init(const unsigned* __restrict__ w) {
    int i = blockIdx.x * blockDim.x + threadIdx.x;
    if (i < NN) { g_cnt[i] = 0; g_fill[i] = 0; }
    if (i == 0) {
        int all0 = 1;
        for (int k = 0; k < 64; k++)
            if (w[2 * k + 1] != 0u) { all0 = 0; break; }
        g_is64 = all0;
    }
}

// ---------------- GEMM body. OUT16=1: write __half to g_h1h; else fp32 ----------------
template <int CO, int XSEL, int OUT16, int YSEL>
__device__ __forceinline__ void gemm_body(const float* __restrict__ Xext,
                                          const float* __restrict__ W,
                                          int row0, int c0) {
    const float* X = (XSEL == 0) ? Xext : g_hb;

    __shared__ float Xt[32][130];
    __shared__ __align__(16) float Ws[32][64];

    int tid = threadIdx.x;
    int tx  = tid & 15;
    int ty  = tid >> 4;

    unsigned long long acc[4][4];
    #pragma unroll
    for (int p = 0; p < 4; p++)
        #pragma unroll
        for (int c = 0; c < 4; c++) acc[p][c] = 0ull;

    for (int ch = 0; ch < 4; ch++) {
        #pragma unroll
        for (int it = 0; it < 4; it++) {
            int idx = it * 256 + tid;
            int cc2 = idx & 31;
            int jj  = idx >> 5;
            *(float2*)&Ws[jj][cc2 * 2] =
                *(const float2*)(W + (size_t)(ch * 32 + jj) * CO + c0 + cc2 * 2);
        }
        #pragma unroll
        for (int it = 0; it < 4; it++) {
            int idx = it * 256 + tid;
            int j4  = idx & 7;
            int r   = idx >> 3;
            float4 v = make_float4(0.f, 0.f, 0.f, 0.f);
            if (row0 + r < NN)
                v = *(const float4*)(X + (size_t)(row0 + r) * 128 + ch * 32 + j4 * 4);
            Xt[j4 * 4 + 0][r] = v.x;
            Xt[j4 * 4 + 1][r] = v.y;
            Xt[j4 * 4 + 2][r] = v.z;
            Xt[j4 * 4 + 3][r] = v.w;
        }
        __syncthreads();

        #pragma unroll
        for (int jj = 0; jj < 32; jj++) {
            unsigned long long a[4];
            #pragma unroll
            for (int p = 0; p < 4; p++)
                a[p] = *(const unsigned long long*)&Xt[jj][ty * 8 + p * 2];
            float4 wv = *(const float4*)&Ws[jj][tx * 4];
            unsigned long long wb[4];
            PACK_DUP(wb[0], wv.x);
            PACK_DUP(wb[1], wv.y);
            PACK_DUP(wb[2], wv.z);
            PACK_DUP(wb[3], wv.w);
            #pragma unroll
            for (int c = 0; c < 4; c++)
                #pragma unroll
                for (int p = 0; p < 4; p++)
                    FMA_F32X2(acc[p][c], a[p], wb[c], acc[p][c]);
        }
        __syncthreads();
    }

    #pragma unroll
    for (int p = 0; p < 4; p++) {
        int r = row0 + ty * 8 + p * 2;
        float4 lo, hi;
        float* lop = &lo.x; float* hip = &hi.x;
        #pragma unroll
        for (int c = 0; c < 4; c++) {
            lop[c] = __uint_as_float((unsigned)(acc[p][c] & 0xffffffffull));
            hip[c] = __uint_as_float((unsigned)(acc[p][c] >> 32));
        }
        if (OUT16) {
            __half2 l01 = __floats2half2_rn(lo.x, lo.y);
            __half2 l23 = __floats2half2_rn(lo.z, lo.w);
            __half2 h01 = __floats2half2_rn(hi.x, hi.y);
            __half2 h23 = __floats2half2_rn(hi.z, hi.w);
            if (r < NN) {
                uint2 v; v.x = *(unsigned*)&l01; v.y = *(unsigned*)&l23;
                *(uint2*)(g_h1h + (size_t)r * 128 + c0 + tx * 4) = v;
            }
            if (r + 1 < NN) {
                uint2 v; v.x = *(unsigned*)&h01; v.y = *(unsigned*)&h23;
                *(uint2*)(g_h1h + (size_t)(r + 1) * 128 + c0 + tx * 4) = v;
            }
        } else {
            float* Y = g_t2;   // only fp32 target left (YSEL kept for future)
            if (r < NN)     *(float4*)(Y + (size_t)r * CO + c0 + tx * 4)       = lo;
            if (r + 1 < NN) *(float4*)(Y + (size_t)(r + 1) * CO + c0 + tx * 4) = hi;
        }
    }
}

// ---------------- fused A: GEMM1 cols 0-63 (fp16 out) || edge count ----------------
__global__ __launch_bounds__(256) void k_fusedA(const float* __restrict__ x,
                                                const float* __restrict__ W1,
                                                const void* __restrict__ ei) {
    if (blockIdx.x < GB1) {
        gemm_body<128, 0, 1, 0>(x, W1, blockIdx.x * 128, 0);
    } else {
        int idx = (blockIdx.x - GB1) * 256 + threadIdx.x;
        if (idx < EE / 2) {
            int d0, d1;
            if (g_is64) {
                ulonglong2 p = ((const ulonglong2*)((const char*)ei + (size_t)EE * 8))[idx];
                d0 = clampn((int)p.x); d1 = clampn((int)p.y);
            } else {
                int2 p = ((const int2*)((const char*)ei + (size_t)EE * 4))[idx];
                d0 = clampn(p.x); d1 = clampn(p.y);
            }
            atomicAdd(&g_cnt[d0], 1);
            atomicAdd(&g_cnt[d1], 1);
        }
    }
}

// ---------------- block sums ----------------
__global__ __launch_bounds__(1024) void k_bsum() {
    __shared__ int s[32];
    int t = threadIdx.x;
    int i = blockIdx.x * 1024 + t;
    int c = (i < NN) ? g_cnt[i] : 0;
    int v = c;
    #pragma unroll
    for (int off = 16; off > 0; off >>= 1)
        v += __shfl_down_sync(0xffffffffu, v, off);
    if ((t & 31) == 0) s[t >> 5] = v;
    __syncthreads();
    if (t < 32) {
        int w = s[t];
        #pragma unroll
        for (int off = 16; off > 0; off >>= 1)
            w += __shfl_down_sync(0xffffffffu, w, off);
        if (t == 0) g_bsum[blockIdx.x] = w;
    }
}

// ---------------- rowptr: local scan of block sums + per-block scan ----------------
__global__ __launch_bounds__(1024) void k_rowptr() {
    __shared__ int sh[1024];
    __shared__ int sb[64];
    __shared__ int s_boff;
    int t = threadIdx.x;

    if (t < 64) sb[t] = (t < NB_SCAN) ? g_bsum[t] : 0;
    __syncthreads();
    #pragma unroll
    for (int off = 1; off < 64; off <<= 1) {
        int u = (t < 64 && t >= off) ? sb[t - off] : 0;
        __syncthreads();
        if (t < 64) sb[t] += u;
        __syncthreads();
    }
    if (t == 0) s_boff = (blockIdx.x == 0) ? 0 : sb[blockIdx.x - 1];

    int i = blockIdx.x * 1024 + t;
    int c = (i < NN) ? g_cnt[i] : 0;
    sh[t] = c;
    __syncthreads();
    #pragma unroll
    for (int off = 1; off < 1024; off <<= 1) {
        int u = (t >= off) ? sh[t - off] : 0;
        __syncthreads();
        sh[t] += u;
        __syncthreads();
    }
    if (i < NN) {
        g_rowptr[i] = sh[t] - c + s_boff;
        g_dinv[i]   = rsqrtf((float)(c + 1));
    }
    if (i == 0) g_rowptr[NN] = EE;
}

// ---------------- fused B: GEMM1 cols 64-127 (fp16 out) || edge scatter ----------------
__global__ __launch_bounds__(256) void k_fusedB(const float* __restrict__ x,
                                                const float* __restrict__ W1,
                                                const void* __restrict__ ei) {
    if (blockIdx.x < GB1) {
        gemm_body<128, 0, 1, 0>(x, W1, blockIdx.x * 128, 64);
    } else {
        int idx = (blockIdx.x - GB1) * 256 + threadIdx.x;
        if (idx < EE / 2) {
            int s0, s1, d0, d1;
            if (g_is64) {
                ulonglong2 ps = ((const ulonglong2*)ei)[idx];
                ulonglong2 pd = ((const ulonglong2*)((const char*)ei + (size_t)EE * 8))[idx];
                s0 = clampn((int)ps.x); s1 = clampn((int)ps.y);
                d0 = clampn((int)pd.x); d1 = clampn((int)pd.y);
            } else {
                int2 ps = ((const int2*)ei)[idx];
                int2 pd = ((const int2*)((const char*)ei + (size_t)EE * 4))[idx];
                s0 = clampn(ps.x); s1 = clampn(ps.y);
                d0 = clampn(pd.x); d1 = clampn(pd.y);
            }
            int p0 = g_rowptr[d0] + atomicAdd(&g_fill[d0], 1);
            g_col[p0] = s0;
            int p1 = g_rowptr[d1] + atomicAdd(&g_fill[d1], 1);
            g_col[p1] = s1;
        }
    }
}

// ---------------- standalone GEMM (layer 2, fp32 in/out) ----------------
__global__ __launch_bounds__(256) void k_gemm2(const float* __restrict__ W) {
    gemm_body<64, 1, 0, 1>(nullptr, W, blockIdx.x * 128, 0);
}

// ---------------- agg layer 1: fp16 gather (C=128), fp32 accum -> g_hb, ReLU ----------------
__global__ __launch_bounds__(256) void k_agg1(const float* __restrict__ bias) {
    int w    = (blockIdx.x * 256 + threadIdx.x) >> 5;
    int lane = threadIdx.x & 31;
    if (w >= NN) return;
    float di = g_dinv[w];
    float acc0, acc1, acc2, acc3;

    {   // self loop
        float sn = di * di;
        uint2 raw = *(const uint2*)(g_h1h + (size_t)w * 128 + lane * 4);
        float2 fa = __half22float2(*(__half2*)&raw.x);
        float2 fb = __half22float2(*(__half2*)&raw.y);
        acc0 = fa.x * sn; acc1 = fa.y * sn; acc2 = fb.x * sn; acc3 = fb.y * sn;
    }

    int beg = g_rowptr[w];
    int end = g_rowptr[w + 1];
    int j   = beg;

    for (; j + 4 <= end; j += 4) {
        int s0 = g_col[j + 0], s1 = g_col[j + 1];
        int s2 = g_col[j + 2], s3 = g_col[j + 3];
        float n0 = g_dinv[s0] * di, n1 = g_dinv[s1] * di;
        float n2 = g_dinv[s2] * di, n3 = g_dinv[s3] * di;
        uint2 r0 = *(const uint2*)(g_h1h + (size_t)s0 * 128 + lane * 4);
        uint2 r1 = *(const uint2*)(g_h1h + (size_t)s1 * 128 + lane * 4);
        uint2 r2 = *(const uint2*)(g_h1h + (size_t)s2 * 128 + lane * 4);
        uint2 r3 = *(const uint2*)(g_h1h + (size_t)s3 * 128 + lane * 4);
        float2 a0 = __half22float2(*(__half2*)&r0.x), b0 = __half22float2(*(__half2*)&r0.y);
        float2 a1 = __half22float2(*(__half2*)&r1.x), b1v = __half22float2(*(__half2*)&r1.y);
        float2 a2 = __half22float2(*(__half2*)&r2.x), b2v = __half22float2(*(__half2*)&r2.y);
        float2 a3 = __half22float2(*(__half2*)&r3.x), b3v = __half22float2(*(__half2*)&r3.y);
        acc0 += a0.x * n0; acc1 += a0.y * n0; acc2 += b0.x * n0; acc3 += b0.y * n0;
        acc0 += a1.x * n1; acc1 += a1.y * n1; acc2 += b1v.x * n1; acc3 += b1v.y * n1;
        acc0 += a2.x * n2; acc1 += a2.y * n2; acc2 += b2v.x * n2; acc3 += b2v.y * n2;
        acc0 += a3.x * n3; acc1 += a3.y * n3; acc2 += b3v.x * n3; acc3 += b3v.y * n3;
    }
    for (; j < end; j++) {
        int   s   = g_col[j];
        float nrm = g_dinv[s] * di;
        uint2 raw = *(const uint2*)(g_h1h + (size_t)s * 128 + lane * 4);
        float2 fa = __half22float2(*(__half2*)&raw.x);
        float2 fb = __half22float2(*(__half2*)&raw.y);
        acc0 += fa.x * nrm; acc1 += fa.y * nrm; acc2 += fb.x * nrm; acc3 += fb.y * nrm;
    }

    float4 r;
    r.x = fmaxf(acc0 + bias[lane * 4 + 0], 0.f);
    r.y = fmaxf(acc1 + bias[lane * 4 + 1], 0.f);
    r.z = fmaxf(acc2 + bias[lane * 4 + 2], 0.f);
    r.w = fmaxf(acc3 + bias[lane * 4 + 3], 0.f);
    *(float4*)(g_hb + (size_t)w * 128 + lane * 4) = r;
}

// ---------------- agg layer 2: fp32 gather (C=64) -> out ----------------
__global__ __launch_bounds__(256) void k_agg2(const float* __restrict__ bias,
                                              float* __restrict__ out) {
    int w    = (blockIdx.x * 256 + threadIdx.x) >> 5;
    int lane = threadIdx.x & 31;
    if (w >= NN) return;
    float di = g_dinv[w];
    float acc0, acc1;

    {
        float sn = di * di;
        float2 v = *(const float2*)(g_t2 + (size_t)w * 64 + lane * 2);
        acc0 = v.x * sn; acc1 = v.y * sn;
    }

    int beg = g_rowptr[w];
    int end = g_rowptr[w + 1];
    int j   = beg;

    for (; j + 4 <= end; j += 4) {
        int s0 = g_col[j + 0], s1 = g_col[j + 1];
        int s2 = g_col[j + 2], s3 = g_col[j + 3];
        float n0 = g_dinv[s0] * di, n1 = g_dinv[s1] * di;
        float n2 = g_dinv[s2] * di, n3 = g_dinv[s3] * di;
        float2 v0 = *(const float2*)(g_t2 + (size_t)s0 * 64 + lane * 2);
        float2 v1 = *(const float2*)(g_t2 + (size_t)s1 * 64 + lane * 2);
        float2 v2 = *(const float2*)(g_t2 + (size_t)s2 * 64 + lane * 2);
        float2 v3 = *(const float2*)(g_t2 + (size_t)s3 * 64 + lane * 2);
        acc0 += v0.x * n0; acc1 += v0.y * n0;
        acc0 += v1.x * n1; acc1 += v1.y * n1;
        acc0 += v2.x * n2; acc1 += v2.y * n2;
        acc0 += v3.x * n3; acc1 += v3.y * n3;
    }
    for (; j < end; j++) {
        int   s   = g_col[j];
        float nrm = g_dinv[s] * di;
        float2 v = *(const float2*)(g_t2 + (size_t)s * 64 + lane * 2);
        acc0 += v.x * nrm; acc1 += v.y * nrm;
    }

    float2 r;
    r.x = acc0 + bias[lane * 2 + 0];
    r.y = acc1 + bias[lane * 2 + 1];
    *(float2*)(out + (size_t)w * 64 + lane * 2) = r;
}

// ---------------- launch ----------------
extern "C" void kernel_launch(void* const* d_in, const int* in_sizes, int n_in,
                              void* d_out, int out_size) {
    const float* x   = (const float*)d_in[0];
    const void*  ei  = d_in[1];
    const float* W1  = (const float*)d_in[2];
    const float* b1  = (const float*)d_in[3];
    const float* W2  = (const float*)d_in[4];
    const float* b2  = (const float*)d_in[5];
    float*       out = (float*)d_out;

    k_init<<<(NN + 255) / 256, 256>>>((const unsigned*)ei);
    k_fusedA<<<GB1 + EB2, 256>>>(x, W1, ei);   // gemm1 half0 || count
    k_bsum<<<NB_SCAN, 1024>>>();
    k_rowptr<<<NB_SCAN, 1024>>>();
    k_fusedB<<<GB1 + EB2, 256>>>(x, W1, ei);   // gemm1 half1 || scatter

    k_agg1<<<(NN * 32 + 255) / 256, 256>>>(b1);
    k_gemm2<<<GB1, 256>>>(W2);
    k_agg2<<<(NN * 32 + 255) / 256, 256>>>(b2, out);
}

// round 9
// speedup vs baseline: 2.1429x; 1.0149x over previous
#include <cuda_runtime.h>
#include <cuda_fp16.h>

#define NN 50000
#define EE 800000
#define NB_SCAN 49    // ceil(50000/1024)
#define GB1 391       // ceil(50000/128) gemm row-tiles
#define EB2 1563      // ceil(400000/256) edge-pair blocks

// ---------------- scratch ----------------
__device__ int   g_is64;
__device__ int   g_cnt[NN];
__device__ int   g_fill[NN];
__device__ int   g_rowptr[NN + 1];
__device__ int   g_col[EE];
__device__ int   g_bsum[64];
__device__ __align__(16) float  g_dinv[NN];
__device__ __align__(16) __half g_h1h[NN * 128];   // x @ W1, fp16
__device__ __align__(16) float  g_hb[NN * 128];    // relu(agg1 + b1), fp32
__device__ __align__(16) __half g_t2h[NN * 64];    // hb @ W2, fp16

#define FMA_F32X2(d, a, b, c) \
    asm("fma.rn.f32x2 %0, %1, %2, %3;" : "=l"(d) : "l"(a), "l"(b), "l"(c))
#define PACK_DUP(out, w) \
    asm("mov.b64 %0, {%1, %2};" : "=l"(out) : "f"(w), "f"(w))

__device__ __forceinline__ int clampn(int v) {
    if (v < 0) v = 0;
    if (v >= NN) v = NN - 1;
    return v;
}

// ---------------- init: zero counters + dtype sniff ----------------
__global__ void k_init(const unsigned* __restrict__ w) {
    int i = blockIdx.x * blockDim.x + threadIdx.x;
    if (i < NN) { g_cnt[i] = 0; g_fill[i] = 0; }
    if (i == 0) {
        int all0 = 1;
        for (int k = 0; k < 64; k++)
            if (w[2 * k + 1] != 0u) { all0 = 0; break; }
        g_is64 = all0;
    }
}

// ---------------- GEMM body. fp16 output to H16 (g_h1h CO=128 / g_t2h CO=64) ----------------
template <int CO, int XSEL>
__device__ __forceinline__ void gemm_body(const float* __restrict__ Xext,
                                          const float* __restrict__ W,
                                          __half* __restrict__ H16,
                                          int row0, int c0) {
    const float* X = (XSEL == 0) ? Xext : g_hb;

    __shared__ float Xt[32][130];
    __shared__ __align__(16) float Ws[32][64];

    int tid = threadIdx.x;
    int tx  = tid & 15;
    int ty  = tid >> 4;

    unsigned long long acc[4][4];
    #pragma unroll
    for (int p = 0; p < 4; p++)
        #pragma unroll
        for (int c = 0; c < 4; c++) acc[p][c] = 0ull;

    for (int ch = 0; ch < 4; ch++) {
        #pragma unroll
        for (int it = 0; it < 4; it++) {
            int idx = it * 256 + tid;
            int cc2 = idx & 31;
            int jj  = idx >> 5;
            *(float2*)&Ws[jj][cc2 * 2] =
                *(const float2*)(W + (size_t)(ch * 32 + jj) * CO + c0 + cc2 * 2);
        }
        #pragma unroll
        for (int it = 0; it < 4; it++) {
            int idx = it * 256 + tid;
            int j4  = idx & 7;
            int r   = idx >> 3;
            float4 v = make_float4(0.f, 0.f, 0.f, 0.f);
            if (row0 + r < NN)
                v = *(const float4*)(X + (size_t)(row0 + r) * 128 + ch * 32 + j4 * 4);
            Xt[j4 * 4 + 0][r] = v.x;
            Xt[j4 * 4 + 1][r] = v.y;
            Xt[j4 * 4 + 2][r] = v.z;
            Xt[j4 * 4 + 3][r] = v.w;
        }
        __syncthreads();

        #pragma unroll
        for (int jj = 0; jj < 32; jj++) {
            unsigned long long a[4];
            #pragma unroll
            for (int p = 0; p < 4; p++)
                a[p] = *(const unsigned long long*)&Xt[jj][ty * 8 + p * 2];
            float4 wv = *(const float4*)&Ws[jj][tx * 4];
            unsigned long long wb[4];
            PACK_DUP(wb[0], wv.x);
            PACK_DUP(wb[1], wv.y);
            PACK_DUP(wb[2], wv.z);
            PACK_DUP(wb[3], wv.w);
            #pragma unroll
            for (int c = 0; c < 4; c++)
                #pragma unroll
                for (int p = 0; p < 4; p++)
                    FMA_F32X2(acc[p][c], a[p], wb[c], acc[p][c]);
        }
        __syncthreads();
    }

    #pragma unroll
    for (int p = 0; p < 4; p++) {
        int r = row0 + ty * 8 + p * 2;
        float4 lo, hi;
        float* lop = &lo.x; float* hip = &hi.x;
        #pragma unroll
        for (int c = 0; c < 4; c++) {
            lop[c] = __uint_as_float((unsigned)(acc[p][c] & 0xffffffffull));
            hip[c] = __uint_as_float((unsigned)(acc[p][c] >> 32));
        }
        __half2 l01 = __floats2half2_rn(lo.x, lo.y);
        __half2 l23 = __floats2half2_rn(lo.z, lo.w);
        __half2 h01 = __floats2half2_rn(hi.x, hi.y);
        __half2 h23 = __floats2half2_rn(hi.z, hi.w);
        if (r < NN) {
            uint2 v; v.x = *(unsigned*)&l01; v.y = *(unsigned*)&l23;
            *(uint2*)(H16 + (size_t)r * CO + c0 + tx * 4) = v;
        }
        if (r + 1 < NN) {
            uint2 v; v.x = *(unsigned*)&h01; v.y = *(unsigned*)&h23;
            *(uint2*)(H16 + (size_t)(r + 1) * CO + c0 + tx * 4) = v;
        }
    }
}

// ---------------- fused A: GEMM1 cols 0-63 || edge count ----------------
__global__ __launch_bounds__(256) void k_fusedA(const float* __restrict__ x,
                                                const float* __restrict__ W1,
                                                const void* __restrict__ ei) {
    if (blockIdx.x < GB1) {
        gemm_body<128, 0>(x, W1, g_h1h, blockIdx.x * 128, 0);
    } else {
        int idx = (blockIdx.x - GB1) * 256 + threadIdx.x;
        if (idx < EE / 2) {
            int d0, d1;
            if (g_is64) {
                ulonglong2 p = ((const ulonglong2*)((const char*)ei + (size_t)EE * 8))[idx];
                d0 = clampn((int)p.x); d1 = clampn((int)p.y);
            } else {
                int2 p = ((const int2*)((const char*)ei + (size_t)EE * 4))[idx];
                d0 = clampn(p.x); d1 = clampn(p.y);
            }
            atomicAdd(&g_cnt[d0], 1);
            atomicAdd(&g_cnt[d1], 1);
        }
    }
}

// ---------------- block sums ----------------
__global__ __launch_bounds__(1024) void k_bsum() {
    __shared__ int s[32];
    int t = threadIdx.x;
    int i = blockIdx.x * 1024 + t;
    int c = (i < NN) ? g_cnt[i] : 0;
    int v = c;
    #pragma unroll
    for (int off = 16; off > 0; off >>= 1)
        v += __shfl_down_sync(0xffffffffu, v, off);
    if ((t & 31) == 0) s[t >> 5] = v;
    __syncthreads();
    if (t < 32) {
        int w = s[t];
        #pragma unroll
        for (int off = 16; off > 0; off >>= 1)
            w += __shfl_down_sync(0xffffffffu, w, off);
        if (t == 0) g_bsum[blockIdx.x] = w;
    }
}

// ---------------- rowptr ----------------
__global__ __launch_bounds__(1024) void k_rowptr() {
    __shared__ int sh[1024];
    __shared__ int sb[64];
    __shared__ int s_boff;
    int t = threadIdx.x;

    if (t < 64) sb[t] = (t < NB_SCAN) ? g_bsum[t] : 0;
    __syncthreads();
    #pragma unroll
    for (int off = 1; off < 64; off <<= 1) {
        int u = (t < 64 && t >= off) ? sb[t - off] : 0;
        __syncthreads();
        if (t < 64) sb[t] += u;
        __syncthreads();
    }
    if (t == 0) s_boff = (blockIdx.x == 0) ? 0 : sb[blockIdx.x - 1];

    int i = blockIdx.x * 1024 + t;
    int c = (i < NN) ? g_cnt[i] : 0;
    sh[t] = c;
    __syncthreads();
    #pragma unroll
    for (int off = 1; off < 1024; off <<= 1) {
        int u = (t >= off) ? sh[t - off] : 0;
        __syncthreads();
        sh[t] += u;
        __syncthreads();
    }
    if (i < NN) {
        g_rowptr[i] = sh[t] - c + s_boff;
        g_dinv[i]   = rsqrtf((float)(c + 1));
    }
    if (i == 0) g_rowptr[NN] = EE;
}

// ---------------- fused B: GEMM1 cols 64-127 || edge scatter ----------------
__global__ __launch_bounds__(256) void k_fusedB(const float* __restrict__ x,
                                                const float* __restrict__ W1,
                                                const void* __restrict__ ei) {
    if (blockIdx.x < GB1) {
        gemm_body<128, 0>(x, W1, g_h1h, blockIdx.x * 128, 64);
    } else {
        int idx = (blockIdx.x - GB1) * 256 + threadIdx.x;
        if (idx < EE / 2) {
            int s0, s1, d0, d1;
            if (g_is64) {
                ulonglong2 ps = ((const ulonglong2*)ei)[idx];
                ulonglong2 pd = ((const ulonglong2*)((const char*)ei + (size_t)EE * 8))[idx];
                s0 = clampn((int)ps.x); s1 = clampn((int)ps.y);
                d0 = clampn((int)pd.x); d1 = clampn((int)pd.y);
            } else {
                int2 ps = ((const int2*)ei)[idx];
                int2 pd = ((const int2*)((const char*)ei + (size_t)EE * 4))[idx];
                s0 = clampn(ps.x); s1 = clampn(ps.y);
                d0 = clampn(pd.x); d1 = clampn(pd.y);
            }
            int p0 = g_rowptr[d0] + atomicAdd(&g_fill[d0], 1);
            g_col[p0] = s0;
            int p1 = g_rowptr[d1] + atomicAdd(&g_fill[d1], 1);
            g_col[p1] = s1;
        }
    }
}

// ---------------- standalone GEMM (layer 2: hb fp32 in, t2 fp16 out) ----------------
__global__ __launch_bounds__(256) void k_gemm2(const float* __restrict__ W) {
    gemm_body<64, 1>(nullptr, W, g_t2h, blockIdx.x * 128, 0);
}

// ---------------- agg layer 1: fp16 gather (C=128) -> g_hb fp32, ReLU ----------------
__global__ __launch_bounds__(256) void k_agg1(const float* __restrict__ bias) {
    int w    = (blockIdx.x * 256 + threadIdx.x) >> 5;
    int lane = threadIdx.x & 31;
    if (w >= NN) return;
    float di = g_dinv[w];
    float acc0, acc1, acc2, acc3;

    {
        float sn = di * di;
        uint2 raw = *(const uint2*)(g_h1h + (size_t)w * 128 + lane * 4);
        float2 fa = __half22float2(*(__half2*)&raw.x);
        float2 fb = __half22float2(*(__half2*)&raw.y);
        acc0 = fa.x * sn; acc1 = fa.y * sn; acc2 = fb.x * sn; acc3 = fb.y * sn;
    }

    int beg = g_rowptr[w];
    int end = g_rowptr[w + 1];
    int j   = beg;

    for (; j + 4 <= end; j += 4) {
        int s0 = g_col[j + 0], s1 = g_col[j + 1];
        int s2 = g_col[j + 2], s3 = g_col[j + 3];
        float n0 = g_dinv[s0] * di, n1 = g_dinv[s1] * di;
        float n2 = g_dinv[s2] * di, n3 = g_dinv[s3] * di;
        uint2 r0 = *(const uint2*)(g_h1h + (size_t)s0 * 128 + lane * 4);
        uint2 r1 = *(const uint2*)(g_h1h + (size_t)s1 * 128 + lane * 4);
        uint2 r2 = *(const uint2*)(g_h1h + (size_t)s2 * 128 + lane * 4);
        uint2 r3 = *(const uint2*)(g_h1h + (size_t)s3 * 128 + lane * 4);
        float2 a0 = __half22float2(*(__half2*)&r0.x), b0 = __half22float2(*(__half2*)&r0.y);
        float2 a1 = __half22float2(*(__half2*)&r1.x), b1v = __half22float2(*(__half2*)&r1.y);
        float2 a2 = __half22float2(*(__half2*)&r2.x), b2v = __half22float2(*(__half2*)&r2.y);
        float2 a3 = __half22float2(*(__half2*)&r3.x), b3v = __half22float2(*(__half2*)&r3.y);
        acc0 += a0.x * n0; acc1 += a0.y * n0; acc2 += b0.x * n0; acc3 += b0.y * n0;
        acc0 += a1.x * n1; acc1 += a1.y * n1; acc2 += b1v.x * n1; acc3 += b1v.y * n1;
        acc0 += a2.x * n2; acc1 += a2.y * n2; acc2 += b2v.x * n2; acc3 += b2v.y * n2;
        acc0 += a3.x * n3; acc1 += a3.y * n3; acc2 += b3v.x * n3; acc3 += b3v.y * n3;
    }
    for (; j < end; j++) {
        int   s   = g_col[j];
        float nrm = g_dinv[s] * di;
        uint2 raw = *(const uint2*)(g_h1h + (size_t)s * 128 + lane * 4);
        float2 fa = __half22float2(*(__half2*)&raw.x);
        float2 fb = __half22float2(*(__half2*)&raw.y);
        acc0 += fa.x * nrm; acc1 += fa.y * nrm; acc2 += fb.x * nrm; acc3 += fb.y * nrm;
    }

    float4 r;
    r.x = fmaxf(acc0 + bias[lane * 4 + 0], 0.f);
    r.y = fmaxf(acc1 + bias[lane * 4 + 1], 0.f);
    r.z = fmaxf(acc2 + bias[lane * 4 + 2], 0.f);
    r.w = fmaxf(acc3 + bias[lane * 4 + 3], 0.f);
    *(float4*)(g_hb + (size_t)w * 128 + lane * 4) = r;
}

// ---------------- agg layer 2: fp16 gather (C=64) -> out fp32 ----------------
__global__ __launch_bounds__(256) void k_agg2(const float* __restrict__ bias,
                                              float* __restrict__ out) {
    int w    = (blockIdx.x * 256 + threadIdx.x) >> 5;
    int lane = threadIdx.x & 31;
    if (w >= NN) return;
    float di = g_dinv[w];
    float acc0, acc1;

    {
        float sn = di * di;
        unsigned raw = *(const unsigned*)(g_t2h + (size_t)w * 64 + lane * 2);
        float2 v = __half22float2(*(__half2*)&raw);
        acc0 = v.x * sn; acc1 = v.y * sn;
    }

    int beg = g_rowptr[w];
    int end = g_rowptr[w + 1];
    int j   = beg;

    for (; j + 4 <= end; j += 4) {
        int s0 = g_col[j + 0], s1 = g_col[j + 1];
        int s2 = g_col[j + 2], s3 = g_col[j + 3];
        float n0 = g_dinv[s0] * di, n1 = g_dinv[s1] * di;
        float n2 = g_dinv[s2] * di, n3 = g_dinv[s3] * di;
        unsigned r0 = *(const unsigned*)(g_t2h + (size_t)s0 * 64 + lane * 2);
        unsigned r1 = *(const unsigned*)(g_t2h + (size_t)s1 * 64 + lane * 2);
        unsigned r2 = *(const unsigned*)(g_t2h + (size_t)s2 * 64 + lane * 2);
        unsigned r3 = *(const unsigned*)(g_t2h + (size_t)s3 * 64 + lane * 2);
        float2 v0 = __half22float2(*(__half2*)&r0);
        float2 v1 = __half22float2(*(__half2*)&r1);
        float2 v2 = __half22float2(*(__half2*)&r2);
        float2 v3 = __half22float2(*(__half2*)&r3);
        acc0 += v0.x * n0; acc1 += v0.y * n0;
        acc0 += v1.x * n1; acc1 += v1.y * n1;
        acc0 += v2.x * n2; acc1 += v2.y * n2;
        acc0 += v3.x * n3; acc1 += v3.y * n3;
    }
    for (; j < end; j++) {
        int   s   = g_col[j];
        float nrm = g_dinv[s] * di;
        unsigned raw = *(const unsigned*)(g_t2h + (size_t)s * 64 + lane * 2);
        float2 v = __half22float2(*(__half2*)&raw);
        acc0 += v.x * nrm; acc1 += v.y * nrm;
    }

    float2 r;
    r.x = acc0 + bias[lane * 2 + 0];
    r.y = acc1 + bias[lane * 2 + 1];
    *(float2*)(out + (size_t)w * 64 + lane * 2) = r;
}

// ---------------- launch ----------------
extern "C" void kernel_launch(void* const* d_in, const int* in_sizes, int n_in,
                              void* d_out, int out_size) {
    const float* x   = (const float*)d_in[0];
    const void*  ei  = d_in[1];
    const float* W1  = (const float*)d_in[2];
    const float* b1  = (const float*)d_in[3];
    const float* W2  = (const float*)d_in[4];
    const float* b2  = (const float*)d_in[5];
    float*       out = (float*)d_out;

    k_init<<<(NN + 255) / 256, 256>>>((const unsigned*)ei);
    k_fusedA<<<GB1 + EB2, 256>>>(x, W1, ei);   // gemm1 half0 || count
    k_bsum<<<NB_SCAN, 1024>>>();
    k_rowptr<<<NB_SCAN, 1024>>>();
    k_fusedB<<<GB1 + EB2, 256>>>(x, W1, ei);   // gemm1 half1 || scatter

    k_agg1<<<(NN * 32 + 255) / 256, 256>>>(b1);
    k_gemm2<<<GB1, 256>>>(W2);
    k_agg2<<<(NN * 32 + 255) / 256, 256>>>(b2, out);
}